// round 15
// baseline (speedup 1.0000x reference)
#include <cuda_runtime.h>
#include <cuda_bf16.h>
#include <math.h>
#include <stdint.h>

// ---------------- problem constants ----------------
#define U_NODES 40000
#define I_NODES 30000
#define N_NODES 70000
#define D_LAT   128
#define D_X     64

// ---------------- scratch layout (floats) ----------------
static const size_t SZ_X     = (size_t)N_NODES * D_LAT;      // 8,960,000
static const size_t SZ_X64   = (size_t)N_NODES * D_X;        // 4,480,000

static const size_t OFF_TFEAT = 0;                     // I*128
static const size_t R_X   = 4000000;                   // x -> rep
static const size_t R_AGG = R_X + 3 * SZ_X;            // agg128 -> x64 + agg64
static const size_t R_H   = R_AGG + 3 * SZ_X;          // h -> h64
static const size_t OFF_CSR = R_H + 3 * SZ_X;          // int scratch
static const size_t OFF_WF  = OFF_CSR + 700000;        // tf32 weight fragments
static const size_t SCRATCH_TOTAL = OFF_WF + 190000;

__device__ float g_scratch[SCRATCH_TOTAL];

// int-scratch offsets (ints within OFF_CSR)
#define ICUR  0
#define IRP   70016
#define IBSUM 140032
#define ICOL  140320
#define IWRP  640320

// weight-fragment offsets (words within OFF_WF)
#define WF_MLP  0
#define WF_LIN1 49152
#define WF_G1   73728
#define WF_LIN2 98304
#define WF_G2   110592
#define WF_C1   122880
#define WF_C2   172032
#define WF_TOTAL 184320

// ---------------- helpers ----------------
__device__ __forceinline__ float lrelu(float v) { return v >= 0.0f ? v : 0.01f * v; }

__device__ __forceinline__ float warp_sum(float v) {
#pragma unroll
    for (int o = 16; o > 0; o >>= 1) v += __shfl_xor_sync(0xFFFFFFFFu, v, o);
    return v;
}

__device__ __forceinline__ uint32_t f2tf(float f) {
    uint32_t r;
    asm("cvt.rna.tf32.f32 %0, %1;" : "=r"(r) : "f"(f));
    return r;
}

__device__ __forceinline__ void mma_tf32(float4& d, const uint32_t* a, const uint32_t* b) {
    asm volatile(
        "mma.sync.aligned.m16n8k8.row.col.f32.tf32.tf32.f32 "
        "{%0,%1,%2,%3}, {%4,%5,%6,%7}, {%8,%9}, {%0,%1,%2,%3};"
        : "+f"(d.x), "+f"(d.y), "+f"(d.z), "+f"(d.w)
        : "r"(a[0]), "r"(a[1]), "r"(a[2]), "r"(a[3]), "r"(b[0]), "r"(b[1]));
}

__device__ __forceinline__ void acc4(float4& a, float4 v) {
    a.x += v.x; a.y += v.y; a.z += v.z; a.w += v.w;
}
__device__ __forceinline__ void acc2(float2& a, float2 v) { a.x += v.x; a.y += v.y; }

// ---- A smem tile fill (fragment-order layout + k8 lane swizzle) ----
template <int BM, int BK>
__device__ __forceinline__ void fill_A(uint32_t* As, const float* __restrict__ A,
                                       int m0, int M, int lda, int k0) {
    const int NF4 = BM * BK / 4 / 256;
    int tid = threadIdx.x;
#pragma unroll
    for (int p = 0; p < NF4; p++) {
        int f = tid + p * 256;
        int m = f / (BK / 4);
        int k4 = f % (BK / 4);
        int gm = m0 + m;
        float4 v = make_float4(0.f, 0.f, 0.f, 0.f);
        if (gm < M) v = *(const float4*)&A[(size_t)gm * lda + k0 + k4 * 4];
        int k8 = k4 >> 1;
        int tm = m >> 4;
        int lane_base = (m & 7) * 4;
        int reg = (((m & 15) >= 8) ? 1 : 0) + ((k4 & 1) ? 2 : 0);
        uint32_t* blk = As + (size_t)((k8 * (BM / 16) + tm) * 32) * 4 + reg;
        blk[((lane_base + 0) ^ k8) * 4] = f2tf(v.x);
        blk[((lane_base + 1) ^ k8) * 4] = f2tf(v.y);
        blk[((lane_base + 2) ^ k8) * 4] = f2tf(v.z);
        blk[((lane_base + 3) ^ k8) * 4] = f2tf(v.w);
    }
}

// ---------- weight prep: write tf32 fragments for the full K range ----------
__global__ void prep_weights(const float* __restrict__ mlp_w, const float* __restrict__ lin1_w,
                             const float* __restrict__ g1_w, const float* __restrict__ lin2_w,
                             const float* __restrict__ g2_w, const float* __restrict__ conv1_w,
                             const float* __restrict__ conv2_w, uint32_t* __restrict__ wf) {
    int i = blockIdx.x * blockDim.x + threadIdx.x;
    if (i >= WF_TOTAL) return;
    const float* src; int K, N, rel; bool tr;
    if (i < WF_LIN1)      { src = mlp_w;  K = 128; N = 128; tr = true;  rel = i; }
    else if (i < WF_G1)   { src = lin1_w; K = 128; N = 64;  tr = true;  rel = i - WF_LIN1; }
    else if (i < WF_LIN2) { src = g1_w;   K = 128; N = 64;  tr = true;  rel = i - WF_G1; }
    else if (i < WF_G2)   { src = lin2_w; K = 64;  N = 64;  tr = true;  rel = i - WF_LIN2; }
    else if (i < WF_C1)   { src = g2_w;   K = 64;  N = 64;  tr = true;  rel = i - WF_G2; }
    else if (i < WF_C2)   { src = conv1_w; K = 128; N = 128; tr = false; rel = i - WF_C1; }
    else                  { src = conv2_w; K = 64;  N = 64;  tr = false; rel = i - WF_C2; }
    int perz = K * N;
    int z = rel / perz, w = rel % perz;
    int reg = w & 1, q = w >> 1, lane = q & 31, idx = q >> 5;
    int tn = idx % (N / 8), k8 = idx / (N / 8);
    int n = tn * 8 + (lane >> 2);
    int k = k8 * 8 + (lane & 3) + reg * 4;
    float v = tr ? src[((size_t)z * N + n) * K + k]
                 : src[((size_t)z * K + k) * N + n];
    wf[i] = f2tf(v);
}

// ---------- batched TC GEMM: BM=128, B fragments from gmem ----------
template <int K, int BK, int BN, bool BIAS, bool LRELU, bool NORM>
__global__ __launch_bounds__(256, 2) void gemm_tc_b(
    const float* __restrict__ Aa, const float* __restrict__ Ab, const float* __restrict__ Ac,
    const uint32_t* __restrict__ Bf, size_t sBf,
    const float* __restrict__ bias, size_t sbias,
    float* __restrict__ C, size_t sC, int M, int ldc) {
    const int BM = 128;
    const int NJ = BN / 16;
    __shared__ __align__(16) uint32_t As[BM * BK];
    __shared__ float rowss[BM];
    int z = blockIdx.z;
    const float* A = (z == 0) ? Aa : (z == 1) ? Ab : Ac;
    const uint32_t* Bfz = Bf + (size_t)z * sBf;
    const float* biasz = BIAS ? bias + (size_t)z * sbias : nullptr;
    float* Cz = C + (size_t)z * sC;

    int tid = threadIdx.x, lane = tid & 31, w = tid >> 5;
    int wm = w & 3, wn = w >> 2;
    int m0 = blockIdx.x * BM;

    float4 acc[2][NJ];
#pragma unroll
    for (int i = 0; i < 2; i++)
#pragma unroll
        for (int j = 0; j < NJ; j++) acc[i][j] = make_float4(0.f, 0.f, 0.f, 0.f);

    for (int k0 = 0; k0 < K; k0 += BK) {
        fill_A<BM, BK>(As, A, m0, M, K, k0);
        __syncthreads();
#pragma unroll
        for (int k8 = 0; k8 < BK / 8; k8++) {
            int k8g = (k0 >> 3) + k8;
            uint32_t a[2][4], b[NJ][2];
#pragma unroll
            for (int i = 0; i < 2; i++) {
                int tm = wm * 2 + i;
                *(uint4*)a[i] = *(const uint4*)&As[(size_t)((k8 * (BM / 16) + tm) * 32 + (lane ^ k8)) * 4];
            }
#pragma unroll
            for (int j = 0; j < NJ; j++) {
                int tn = wn * NJ + j;
                *(uint2*)b[j] = *(const uint2*)&Bfz[(size_t)((k8g * (BN / 8) + tn) * 32 + lane) * 2];
            }
#pragma unroll
            for (int i = 0; i < 2; i++)
#pragma unroll
                for (int j = 0; j < NJ; j++) mma_tf32(acc[i][j], a[i], b[j]);
        }
        __syncthreads();
    }

    int g = lane >> 2, tg = lane & 3;

    if (NORM) {
        if (tid < BM) rowss[tid] = 0.f;
        __syncthreads();
        float ss0[2] = {0.f, 0.f}, ss1[2] = {0.f, 0.f};
#pragma unroll
        for (int i = 0; i < 2; i++)
#pragma unroll
            for (int j = 0; j < NJ; j++) {
                int c = (wn * NJ + j) * 8 + tg * 2;
                float2 bb = *(const float2*)&biasz[c];
                float vx = acc[i][j].x + bb.x, vy = acc[i][j].y + bb.y;
                float vz = acc[i][j].z + bb.x, vw = acc[i][j].w + bb.y;
                ss0[i] += vx * vx + vy * vy;
                ss1[i] += vz * vz + vw * vw;
            }
#pragma unroll
        for (int i = 0; i < 2; i++) {
            atomicAdd(&rowss[wm * 32 + i * 16 + g], ss0[i]);
            atomicAdd(&rowss[wm * 32 + i * 16 + g + 8], ss1[i]);
        }
        __syncthreads();
    }

#pragma unroll
    for (int i = 0; i < 2; i++) {
        int r0 = m0 + wm * 32 + i * 16 + g;
        float s0 = 1.0f, s1 = 1.0f;
        if (NORM) {
            s0 = 1.0f / fmaxf(sqrtf(rowss[wm * 32 + i * 16 + g]), 1e-12f);
            s1 = 1.0f / fmaxf(sqrtf(rowss[wm * 32 + i * 16 + g + 8]), 1e-12f);
        }
#pragma unroll
        for (int j = 0; j < NJ; j++) {
            int c = (wn * NJ + j) * 8 + tg * 2;
            float bx = 0.f, by = 0.f;
            if (BIAS) { float2 bb = *(const float2*)&biasz[c]; bx = bb.x; by = bb.y; }
            float2 v01 = make_float2(acc[i][j].x + bx, acc[i][j].y + by);
            float2 v23 = make_float2(acc[i][j].z + bx, acc[i][j].w + by);
            if (LRELU) {
                v01.x = lrelu(v01.x); v01.y = lrelu(v01.y);
                v23.x = lrelu(v23.x); v23.y = lrelu(v23.y);
            }
            if (NORM) {
                v01.x *= s0; v01.y *= s0;
                v23.x *= s1; v23.y *= s1;
            }
            if (r0 < M)     *(float2*)&Cz[(size_t)r0 * ldc + c] = v01;
            if (r0 + 8 < M) *(float2*)&Cz[(size_t)(r0 + 8) * ldc + c] = v23;
        }
    }
}

// ---- batched dual GEMM, B fragments from gmem ----
template <int K>
__global__ __launch_bounds__(256, 2) void dual_gemm_tc_b(
    const float* __restrict__ A1, size_t sA1,
    const uint32_t* __restrict__ B1f, size_t sB1, const float* __restrict__ b1, size_t sb1,
    const float* __restrict__ A2, size_t sA2,
    const uint32_t* __restrict__ B2f, size_t sB2, const float* __restrict__ b2, size_t sb2,
    const float* __restrict__ idemb, float* __restrict__ out, size_t sOut, int M) {
    const int BM = 128, BK = 32, BN = 64;
    __shared__ __align__(16) uint32_t As1[BM * BK];
    __shared__ __align__(16) uint32_t As2[BM * BK];
    int z = blockIdx.z;
    const float* A1z = A1 + (size_t)z * sA1;
    const float* A2z = A2 + (size_t)z * sA2;
    const uint32_t* B1z = B1f + (size_t)z * sB1;
    const uint32_t* B2z = B2f + (size_t)z * sB2;
    const float* b1z = b1 + (size_t)z * sb1;
    const float* b2z = b2 + (size_t)z * sb2;
    float* outz = out + (size_t)z * sOut;

    int tid = threadIdx.x, lane = tid & 31, w = tid >> 5;
    int wm = w >> 1, wn = w & 1;
    int m0 = blockIdx.x * BM;

    float4 acc1[2][4], acc2[2][4];
#pragma unroll
    for (int i = 0; i < 2; i++)
#pragma unroll
        for (int j = 0; j < 4; j++) {
            acc1[i][j] = make_float4(0.f, 0.f, 0.f, 0.f);
            acc2[i][j] = make_float4(0.f, 0.f, 0.f, 0.f);
        }

    for (int k0 = 0; k0 < K; k0 += BK) {
        fill_A<BM, BK>(As1, A1z, m0, M, K, k0);
        fill_A<BM, BK>(As2, A2z, m0, M, K, k0);
        __syncthreads();
#pragma unroll
        for (int k8 = 0; k8 < BK / 8; k8++) {
            int k8g = (k0 >> 3) + k8;
            uint32_t a1[2][4], a2[2][4], bf1[4][2], bf2[4][2];
#pragma unroll
            for (int i = 0; i < 2; i++) {
                int tm = wm * 2 + i;
                *(uint4*)a1[i] = *(const uint4*)&As1[(size_t)((k8 * (BM / 16) + tm) * 32 + (lane ^ k8)) * 4];
                *(uint4*)a2[i] = *(const uint4*)&As2[(size_t)((k8 * (BM / 16) + tm) * 32 + (lane ^ k8)) * 4];
            }
#pragma unroll
            for (int j = 0; j < 4; j++) {
                int tn = wn * 4 + j;
                *(uint2*)bf1[j] = *(const uint2*)&B1z[(size_t)((k8g * 8 + tn) * 32 + lane) * 2];
                *(uint2*)bf2[j] = *(const uint2*)&B2z[(size_t)((k8g * 8 + tn) * 32 + lane) * 2];
            }
#pragma unroll
            for (int i = 0; i < 2; i++)
#pragma unroll
                for (int j = 0; j < 4; j++) {
                    mma_tf32(acc1[i][j], a1[i], bf1[j]);
                    mma_tf32(acc2[i][j], a2[i], bf2[j]);
                }
        }
        __syncthreads();
    }

    int g = lane >> 2, tg = lane & 3;
#pragma unroll
    for (int i = 0; i < 2; i++) {
        int r0 = m0 + wm * 32 + i * 16 + g;
#pragma unroll
        for (int j = 0; j < 4; j++) {
            int c = wn * 32 + j * 8 + tg * 2;
            float2 bb1 = *(const float2*)&b1z[c];
            float2 bb2 = *(const float2*)&b2z[c];
            if (r0 < M) {
                float2 idv = *(const float2*)&idemb[(size_t)r0 * D_X + c];
                float u1 = lrelu(acc1[i][j].x + bb1.x);
                float u2 = lrelu(acc1[i][j].y + bb1.y);
                float o1 = lrelu(acc2[i][j].x + bb2.x + u1 + idv.x);
                float o2 = lrelu(acc2[i][j].y + bb2.y + u2 + idv.y);
                *(float2*)&outz[(size_t)r0 * D_X + c] = make_float2(o1, o2);
            }
            if (r0 + 8 < M) {
                float2 idv = *(const float2*)&idemb[(size_t)(r0 + 8) * D_X + c];
                float u1 = lrelu(acc1[i][j].z + bb1.x);
                float u2 = lrelu(acc1[i][j].w + bb1.y);
                float o1 = lrelu(acc2[i][j].z + bb2.x + u1 + idv.x);
                float o2 = lrelu(acc2[i][j].w + bb2.y + u2 + idv.y);
                *(float2*)&outz[(size_t)(r0 + 8) * D_X + c] = make_float2(o1, o2);
            }
        }
    }
}

// ---------------- CSR build ----------------
// merged: zero cursor (deg) + words row_ptr in one launch
__global__ void init_misc(int* __restrict__ cursor, const int* __restrict__ words, int W,
                          int* __restrict__ wrp) {
    int i = blockIdx.x * blockDim.x + threadIdx.x;
    if (i < N_NODES + 1) cursor[i] = 0;
    if (i < W) {
        int it = words[i];
        int prev = (i == 0) ? -1 : words[i - 1];
        for (int t = prev + 1; t <= it; t++) wrp[t] = i;
        if (i == W - 1)
            for (int t = it + 1; t <= I_NODES; t++) wrp[t] = W;
    }
}

__global__ void deg_hist(const int* __restrict__ ei, int E, int* __restrict__ deg) {
    int e = blockIdx.x * blockDim.x + threadIdx.x;
    if (e < E) atomicAdd(&deg[ei[E + e]], 1);
}

__global__ void deg_partials(const int* __restrict__ deg, int* __restrict__ bsum, int n) {
    __shared__ int s[256];
    int i = blockIdx.x * 256 + threadIdx.x;
    s[threadIdx.x] = (i < n) ? deg[i] : 0;
    __syncthreads();
    for (int o = 128; o > 0; o >>= 1) {
        if (threadIdx.x < o) s[threadIdx.x] += s[threadIdx.x + o];
        __syncthreads();
    }
    if (threadIdx.x == 0) bsum[blockIdx.x] = s[0];
}

__global__ void deg_scan(const int* __restrict__ deg, const int* __restrict__ bsum,
                         int* __restrict__ rp, int* __restrict__ cursor, int n) {
    __shared__ int s[256];
    __shared__ int off_s;
    int b = blockIdx.x, t = threadIdx.x;
    if (t == 0) {
        int o = 0;
        for (int k = 0; k < b; k++) o += bsum[k];
        off_s = o;
    }
    int i = b * 256 + t;
    int v = (i < n) ? deg[i] : 0;
    s[t] = v;
    __syncthreads();
    for (int o = 1; o < 256; o <<= 1) {
        int add = (t >= o) ? s[t - o] : 0;
        __syncthreads();
        s[t] += add;
        __syncthreads();
    }
    int ex = s[t] - v + off_s;
    if (i < n) { rp[i] = ex; cursor[i] = ex; }
    if (i == n - 1) rp[n] = ex + v;
}

// merged: csr_fill (y==0) + user-row normalize (y==1..3, z = y-1)
__global__ void csr_fill_norm(const int* __restrict__ ei, int E,
                              int* __restrict__ cursor, int* __restrict__ col,
                              const float* __restrict__ pref, float* __restrict__ xbase) {
    if (blockIdx.y == 0) {
        int e = blockIdx.x * blockDim.x + threadIdx.x;
        if (e >= E) return;
        int s = ei[e], d = ei[E + e];
        int pos = atomicAdd(&cursor[d], 1);
        col[pos] = s;
    } else {
        int row = (int)(((long)blockIdx.x * blockDim.x + threadIdx.x) >> 5);
        int lane = threadIdx.x & 31;
        if (row >= U_NODES) return;
        int z = blockIdx.y - 1;
        float* x = xbase + (size_t)z * SZ_X;
        const float* pref_m = pref + (size_t)z * U_NODES * D_LAT;
        float4 v = ((const float4*)(pref_m + (size_t)row * D_LAT))[lane];
        float ss = v.x * v.x + v.y * v.y + v.z * v.z + v.w * v.w;
        ss = warp_sum(ss);
        float s = 1.0f / fmaxf(sqrtf(ss), 1e-12f);
        v.x *= s; v.y *= s; v.z *= s; v.w *= s;
        ((float4*)(x + (size_t)row * D_LAT))[lane] = v;
    }
}

// ---------------- gathers (4-wide, per-modality for L2 residency) ----------------
__global__ void words_gather(const int* __restrict__ rp, const int* __restrict__ words,
                             int W, const float* __restrict__ word_emb,
                             float* __restrict__ tfeat) {
    int it = (int)(((long)blockIdx.x * blockDim.x + threadIdx.x) >> 5);
    int lane = threadIdx.x & 31;
    if (it >= I_NODES) return;
    int beg = rp[it], end = rp[it + 1];
    float4 a = make_float4(0.f, 0.f, 0.f, 0.f);
    int j = beg;
    for (; j + 4 <= end; j += 4) {
        int w0 = words[W + j], w1 = words[W + j + 1], w2 = words[W + j + 2], w3 = words[W + j + 3];
        acc4(a, ((const float4*)(word_emb + (size_t)w0 * D_LAT))[lane]);
        acc4(a, ((const float4*)(word_emb + (size_t)w1 * D_LAT))[lane]);
        acc4(a, ((const float4*)(word_emb + (size_t)w2 * D_LAT))[lane]);
        acc4(a, ((const float4*)(word_emb + (size_t)w3 * D_LAT))[lane]);
    }
    for (; j < end; j++)
        acc4(a, ((const float4*)(word_emb + (size_t)words[W + j] * D_LAT))[lane]);
    float inv = 1.0f / (float)max(end - beg, 1);
    a.x *= inv; a.y *= inv; a.z *= inv; a.w *= inv;
    ((float4*)(tfeat + (size_t)it * D_LAT))[lane] = a;
}

__global__ void gather128(const int* __restrict__ rp, const int* __restrict__ col,
                          const float* __restrict__ x, float* __restrict__ agg) {
    int n = (int)(((long)blockIdx.x * blockDim.x + threadIdx.x) >> 5);
    int lane = threadIdx.x & 31;
    if (n >= N_NODES) return;
    int beg = rp[n], end = rp[n + 1];
    float4 a = make_float4(0.f, 0.f, 0.f, 0.f);
    int j = beg;
    for (; j + 4 <= end; j += 4) {
        int s0 = col[j], s1 = col[j + 1], s2 = col[j + 2], s3 = col[j + 3];
        acc4(a, ((const float4*)(x + (size_t)s0 * D_LAT))[lane]);
        acc4(a, ((const float4*)(x + (size_t)s1 * D_LAT))[lane]);
        acc4(a, ((const float4*)(x + (size_t)s2 * D_LAT))[lane]);
        acc4(a, ((const float4*)(x + (size_t)s3 * D_LAT))[lane]);
    }
    for (; j < end; j++)
        acc4(a, ((const float4*)(x + (size_t)col[j] * D_LAT))[lane]);
    ((float4*)(agg + (size_t)n * D_LAT))[lane] = a;
}

__global__ void gather64(const int* __restrict__ rp, const int* __restrict__ col,
                         const float* __restrict__ x, float* __restrict__ agg) {
    int n = (int)(((long)blockIdx.x * blockDim.x + threadIdx.x) >> 5);
    int lane = threadIdx.x & 31;
    if (n >= N_NODES) return;
    int beg = rp[n], end = rp[n + 1];
    float2 a = make_float2(0.f, 0.f);
    int j = beg;
    for (; j + 4 <= end; j += 4) {
        int s0 = col[j], s1 = col[j + 1], s2 = col[j + 2], s3 = col[j + 3];
        acc2(a, ((const float2*)(x + (size_t)s0 * D_X))[lane]);
        acc2(a, ((const float2*)(x + (size_t)s1 * D_X))[lane]);
        acc2(a, ((const float2*)(x + (size_t)s2 * D_X))[lane]);
        acc2(a, ((const float2*)(x + (size_t)s3 * D_X))[lane]);
    }
    for (; j < end; j++)
        acc2(a, ((const float2*)(x + (size_t)col[j] * D_X))[lane]);
    ((float2*)(agg + (size_t)n * D_X))[lane] = a;
}

// ---------------- final scoring ----------------
__global__ void final_kernel(const float* __restrict__ rep,
                             const int* __restrict__ users, const int* __restrict__ pos,
                             const int* __restrict__ neg, float* __restrict__ out, int Bn) {
    int gw = (int)(((long)blockIdx.x * blockDim.x + threadIdx.x) >> 5);
    int lane = threadIdx.x & 31;
    if (gw >= Bn) return;
    int u = users[gw], p = pos[gw], n = neg[gw];
    const size_t stride = (size_t)N_NODES * D_X;
    const float* r0 = rep;
    const float* r1 = rep + stride;
    const float* r2 = rep + 2 * stride;

    auto ld = [&](const float* base, int node) {
        return ((const float2*)(base + (size_t)node * D_X))[lane];
    };
    float2 t_u = ld(r2, u), t_p = ld(r2, p), t_n = ld(r2, n);
    float2 a_u = ld(r0, u), b_u = ld(r1, u);
    float2 a_p = ld(r0, p), b_p = ld(r1, p);
    float2 a_n = ld(r0, n), b_n = ld(r1, n);

    const float third = 1.0f / 3.0f;
    float2 pu = make_float2((a_u.x + b_u.x + t_u.x) * third, (a_u.y + b_u.y + t_u.y) * third);
    float2 pp = make_float2((a_p.x + b_p.x + t_p.x) * third, (a_p.y + b_p.y + t_p.y) * third);
    float2 pn = make_float2((a_n.x + b_n.x + t_n.x) * third, (a_n.y + b_n.y + t_n.y) * third);

    float prep  = t_u.x * t_p.x + t_u.y * t_p.y;
    float pren  = t_u.x * t_n.x + t_u.y * t_n.y;
    float postp = pu.x * pp.x + pu.y * pp.y;
    float postn = pu.x * pn.x + pu.y * pn.y;

    prep = warp_sum(prep);
    pren = warp_sum(pren);
    postp = warp_sum(postp);
    postn = warp_sum(postn);

    if (lane == 0) {
        float sp = 1.0f / (1.0f + expf(-prep));
        float sn = 1.0f / (1.0f + expf(-pren));
        out[gw]          = postp * sp;
        out[Bn + gw]     = postn * sn;
        out[2 * Bn + gw] = prep;
        out[3 * Bn + gw] = pren;
    }
}

// ---------------- host orchestration ----------------
static inline int nblk(long n, int t) { return (int)((n + t - 1) / t); }

extern "C" void kernel_launch(void* const* d_in, const int* in_sizes, int n_in,
                              void* d_out, int out_size) {
    const float* v_feat   = (const float*)d_in[0];
    const float* a_feat   = (const float*)d_in[1];
    const float* word_emb = (const float*)d_in[2];
    const float* id_emb   = (const float*)d_in[3];
    const float* pref     = (const float*)d_in[4];
    const float* mlp_w    = (const float*)d_in[5];
    const float* mlp_b    = (const float*)d_in[6];
    const float* conv1_w  = (const float*)d_in[7];
    const float* lin1_w   = (const float*)d_in[8];
    const float* lin1_b   = (const float*)d_in[9];
    const float* g1_w     = (const float*)d_in[10];
    const float* g1_b     = (const float*)d_in[11];
    const float* conv2_w  = (const float*)d_in[12];
    const float* lin2_w   = (const float*)d_in[13];
    const float* lin2_b   = (const float*)d_in[14];
    const float* g2_w     = (const float*)d_in[15];
    const float* g2_b     = (const float*)d_in[16];
    const int*   edges    = (const int*)d_in[17];
    const int*   words    = (const int*)d_in[18];
    const int*   users    = (const int*)d_in[19];
    const int*   posn     = (const int*)d_in[20];
    const int*   negn     = (const int*)d_in[21];

    const int E  = in_sizes[17] / 2;   // 500000
    const int W  = in_sizes[18] / 2;   // 600000
    const int Bn = in_sizes[19];       // 2048

    float* sc = nullptr;
    cudaGetSymbolAddress((void**)&sc, g_scratch);

    float* tfeat = sc + OFF_TFEAT;
    float* x     = sc + R_X;                       // stride SZ_X
    float* rep   = sc + R_X;                       // stride SZ_X64 (x dead at dual2)
    float* agg   = sc + R_AGG;                     // stride SZ_X
    float* h     = sc + R_H;                       // stride SZ_X; reused as h64
    float* x64   = sc + R_AGG;                     // stride SZ_X64 (agg dead after conv1)
    float* agg64 = sc + R_AGG + 3 * SZ_X64;        // stride SZ_X64

    int* ib     = (int*)(sc + OFF_CSR);
    int* cursor = ib + ICUR;
    int* rp     = ib + IRP;
    int* bsum   = ib + IBSUM;
    int* col    = ib + ICOL;
    int* wrp    = ib + IWRP;
    uint32_t* wf = (uint32_t*)(sc + OFF_WF);

    const int NB = nblk(N_NODES, 256);
    const int GB = nblk((long)N_NODES * 32, 256);

    // 0: weight fragments (tf32, fragment order)
    prep_weights<<<nblk(WF_TOTAL, 256), 256>>>(mlp_w, lin1_w, g1_w, lin2_w, g2_w,
                                               conv1_w, conv2_w, wf);
    // 1: zero cursor + words row_ptr (merged)
    init_misc<<<nblk(W, 256), 256>>>(cursor, words, W, wrp);
    // 2: t_feat gather-mean
    words_gather<<<nblk((long)I_NODES * 32, 256), 256>>>(wrp, words, W, word_emb, tfeat);
    // 3: mlp GEMM + fused item-row normalize  <-- ncu capture target
    {
        dim3 grid(nblk(I_NODES, 128), 1, 3);
        gemm_tc_b<128, 64, 128, true, false, true><<<grid, 256>>>(
            v_feat, a_feat, tfeat,
            wf + WF_MLP, 128 * 128, mlp_b, 128,
            x + (size_t)U_NODES * D_LAT, SZ_X, I_NODES, 128);
    }
    // 4-6: CSR histogram + scan
    deg_hist<<<nblk(E, 256), 256>>>(edges, E, cursor);
    deg_partials<<<NB, 256>>>(cursor, bsum, N_NODES);
    deg_scan<<<NB, 256>>>(cursor, bsum, rp, cursor, N_NODES);
    // 7: csr_fill + user-row normalize (merged)
    {
        dim3 grid(nblk((long)U_NODES * 32, 256), 4);
        csr_fill_norm<<<grid, 256>>>(edges, E, cursor, col, pref, x);
    }
    // 8-10: layer-1 gather, one modality at a time (72 MB working set -> L2 resident)
    for (int m = 0; m < 3; m++)
        gather128<<<GB, 256>>>(rp, col, x + (size_t)m * SZ_X, agg + (size_t)m * SZ_X);
    // 11: conv1
    {
        dim3 grid(nblk(N_NODES, 128), 1, 3);
        gemm_tc_b<128, 64, 128, false, true, false><<<grid, 256>>>(
            agg, agg + SZ_X, agg + 2 * SZ_X,
            wf + WF_C1, 128 * 128, nullptr, 0,
            h, SZ_X, N_NODES, 128);
    }
    // 12: dual1 -> x64 (into R_AGG; agg dead)
    {
        dim3 grid(nblk(N_NODES, 128), 1, 3);
        dual_gemm_tc_b<128><<<grid, 256>>>(
            x, SZ_X, wf + WF_LIN1, 128 * 64, lin1_b, 64,
            h, SZ_X, wf + WF_G1, 128 * 64, g1_b, 64,
            id_emb, x64, SZ_X64, N_NODES);
    }
    // 13-15: layer-2 gather, per modality
    for (int m = 0; m < 3; m++)
        gather64<<<GB, 256>>>(rp, col, x64 + (size_t)m * SZ_X64, agg64 + (size_t)m * SZ_X64);
    // 16: conv2 -> h64 (R_H reuse)
    {
        dim3 grid(nblk(N_NODES, 128), 1, 3);
        gemm_tc_b<64, 64, 64, false, true, false><<<grid, 256>>>(
            agg64, agg64 + SZ_X64, agg64 + 2 * SZ_X64,
            wf + WF_C2, 64 * 64, nullptr, 0,
            h, SZ_X64, N_NODES, 64);
    }
    // 17: dual2 -> rep (into R_X; x dead)
    {
        dim3 grid(nblk(N_NODES, 128), 1, 3);
        dual_gemm_tc_b<64><<<grid, 256>>>(
            x64, SZ_X64, wf + WF_LIN2, 64 * 64, lin2_b, 64,
            h, SZ_X64, wf + WF_G2, 64 * 64, g2_b, 64,
            id_emb, rep, SZ_X64, N_NODES);
    }
    // 18: final scoring
    final_kernel<<<nblk((long)Bn * 32, 256), 256>>>(rep, users, posn, negn,
                                                    (float*)d_out, Bn);
}

// round 16
// speedup vs baseline: 1.0327x; 1.0327x over previous
#include <cuda_runtime.h>
#include <cuda_bf16.h>
#include <math.h>
#include <stdint.h>

// ---------------- problem constants ----------------
#define U_NODES 40000
#define I_NODES 30000
#define N_NODES 70000
#define D_LAT   128
#define D_X     64

// ---------------- scratch layout (floats) ----------------
static const size_t SZ_X     = (size_t)N_NODES * D_LAT;      // 8,960,000
static const size_t SZ_X64   = (size_t)N_NODES * D_X;        // 4,480,000

static const size_t OFF_TFEAT = 0;                     // I*128
static const size_t R_X   = 4000000;                   // x -> rep
static const size_t R_AGG = R_X + 3 * SZ_X;            // agg128 -> x64 + agg64
static const size_t R_H   = R_AGG + 3 * SZ_X;          // h -> h64
static const size_t OFF_CSR = R_H + 3 * SZ_X;          // int scratch
static const size_t OFF_WF  = OFF_CSR + 700000;        // tf32 weight fragments
static const size_t SCRATCH_TOTAL = OFF_WF + 190000;

__device__ float g_scratch[SCRATCH_TOTAL];

// int-scratch offsets (ints within OFF_CSR)
#define ICUR  0
#define IRP   70016
#define IBSUM 140032
#define ICOL  140320
#define IWRP  640320

// weight-fragment offsets (words within OFF_WF)
#define WF_MLP  0
#define WF_LIN1 49152
#define WF_G1   73728
#define WF_LIN2 98304
#define WF_G2   110592
#define WF_C1   122880
#define WF_C2   172032
#define WF_TOTAL 184320

// ---------------- helpers ----------------
__device__ __forceinline__ float lrelu(float v) { return v >= 0.0f ? v : 0.01f * v; }

__device__ __forceinline__ float warp_sum(float v) {
#pragma unroll
    for (int o = 16; o > 0; o >>= 1) v += __shfl_xor_sync(0xFFFFFFFFu, v, o);
    return v;
}

__device__ __forceinline__ uint32_t f2tf(float f) {
    uint32_t r;
    asm("cvt.rna.tf32.f32 %0, %1;" : "=r"(r) : "f"(f));
    return r;
}

__device__ __forceinline__ void mma_tf32(float4& d, const uint32_t* a, const uint32_t* b) {
    asm volatile(
        "mma.sync.aligned.m16n8k8.row.col.f32.tf32.tf32.f32 "
        "{%0,%1,%2,%3}, {%4,%5,%6,%7}, {%8,%9}, {%0,%1,%2,%3};"
        : "+f"(d.x), "+f"(d.y), "+f"(d.z), "+f"(d.w)
        : "r"(a[0]), "r"(a[1]), "r"(a[2]), "r"(a[3]), "r"(b[0]), "r"(b[1]));
}

__device__ __forceinline__ void acc4(float4& a, float4 v) {
    a.x += v.x; a.y += v.y; a.z += v.z; a.w += v.w;
}
__device__ __forceinline__ void acc2(float2& a, float2 v) { a.x += v.x; a.y += v.y; }

// ---- A smem tile fill (fragment-order layout + k8 lane swizzle) ----
template <int BM, int BK>
__device__ __forceinline__ void fill_A(uint32_t* As, const float* __restrict__ A,
                                       int m0, int M, int lda, int k0) {
    const int NF4 = BM * BK / 4 / 256;
    int tid = threadIdx.x;
#pragma unroll
    for (int p = 0; p < NF4; p++) {
        int f = tid + p * 256;
        int m = f / (BK / 4);
        int k4 = f % (BK / 4);
        int gm = m0 + m;
        float4 v = make_float4(0.f, 0.f, 0.f, 0.f);
        if (gm < M) v = *(const float4*)&A[(size_t)gm * lda + k0 + k4 * 4];
        int k8 = k4 >> 1;
        int tm = m >> 4;
        int lane_base = (m & 7) * 4;
        int reg = (((m & 15) >= 8) ? 1 : 0) + ((k4 & 1) ? 2 : 0);
        uint32_t* blk = As + (size_t)((k8 * (BM / 16) + tm) * 32) * 4 + reg;
        blk[((lane_base + 0) ^ k8) * 4] = f2tf(v.x);
        blk[((lane_base + 1) ^ k8) * 4] = f2tf(v.y);
        blk[((lane_base + 2) ^ k8) * 4] = f2tf(v.z);
        blk[((lane_base + 3) ^ k8) * 4] = f2tf(v.w);
    }
}

// ---------- weight prep: write tf32 fragments for the full K range ----------
__global__ void prep_weights(const float* __restrict__ mlp_w, const float* __restrict__ lin1_w,
                             const float* __restrict__ g1_w, const float* __restrict__ lin2_w,
                             const float* __restrict__ g2_w, const float* __restrict__ conv1_w,
                             const float* __restrict__ conv2_w, uint32_t* __restrict__ wf) {
    int i = blockIdx.x * blockDim.x + threadIdx.x;
    if (i >= WF_TOTAL) return;
    const float* src; int K, N, rel; bool tr;
    if (i < WF_LIN1)      { src = mlp_w;  K = 128; N = 128; tr = true;  rel = i; }
    else if (i < WF_G1)   { src = lin1_w; K = 128; N = 64;  tr = true;  rel = i - WF_LIN1; }
    else if (i < WF_LIN2) { src = g1_w;   K = 128; N = 64;  tr = true;  rel = i - WF_G1; }
    else if (i < WF_G2)   { src = lin2_w; K = 64;  N = 64;  tr = true;  rel = i - WF_LIN2; }
    else if (i < WF_C1)   { src = g2_w;   K = 64;  N = 64;  tr = true;  rel = i - WF_G2; }
    else if (i < WF_C2)   { src = conv1_w; K = 128; N = 128; tr = false; rel = i - WF_C1; }
    else                  { src = conv2_w; K = 64;  N = 64;  tr = false; rel = i - WF_C2; }
    int perz = K * N;
    int z = rel / perz, w = rel % perz;
    int reg = w & 1, q = w >> 1, lane = q & 31, idx = q >> 5;
    int tn = idx % (N / 8), k8 = idx / (N / 8);
    int n = tn * 8 + (lane >> 2);
    int k = k8 * 8 + (lane & 3) + reg * 4;
    float v = tr ? src[((size_t)z * N + n) * K + k]
                 : src[((size_t)z * K + k) * N + n];
    wf[i] = f2tf(v);
}

// ---------- batched TC GEMM, FULL-K A staging: BM=128, one sync total ----------
template <int K, int BN, bool BIAS, bool LRELU, bool NORM>
__global__ __launch_bounds__(256, 2) void gemm_tc_f(
    const float* __restrict__ Aa, const float* __restrict__ Ab, const float* __restrict__ Ac,
    const uint32_t* __restrict__ Bf, size_t sBf,
    const float* __restrict__ bias, size_t sbias,
    float* __restrict__ C, size_t sC, int M, int ldc) {
    const int BM = 128;
    const int NJ = BN / 16;
    extern __shared__ uint32_t As[];           // BM * K words
    __shared__ float rowss[BM];
    int z = blockIdx.z;
    const float* A = (z == 0) ? Aa : (z == 1) ? Ab : Ac;
    const uint32_t* Bfz = Bf + (size_t)z * sBf;
    const float* biasz = BIAS ? bias + (size_t)z * sbias : nullptr;
    float* Cz = C + (size_t)z * sC;

    int tid = threadIdx.x, lane = tid & 31, w = tid >> 5;
    int wm = w & 3, wn = w >> 2;
    int m0 = blockIdx.x * BM;

    float4 acc[2][NJ];
#pragma unroll
    for (int i = 0; i < 2; i++)
#pragma unroll
        for (int j = 0; j < NJ; j++) acc[i][j] = make_float4(0.f, 0.f, 0.f, 0.f);

    // stage the whole A tile once (16 LDG.128 per thread, deep MLP)
    fill_A<BM, K>(As, A, m0, M, K, 0);
    __syncthreads();

#pragma unroll
    for (int k8 = 0; k8 < K / 8; k8++) {
        uint32_t a[2][4], b[NJ][2];
#pragma unroll
        for (int i = 0; i < 2; i++) {
            int tm = wm * 2 + i;
            *(uint4*)a[i] = *(const uint4*)&As[(size_t)((k8 * (BM / 16) + tm) * 32 + (lane ^ k8)) * 4];
        }
#pragma unroll
        for (int j = 0; j < NJ; j++) {
            int tn = wn * NJ + j;
            *(uint2*)b[j] = *(const uint2*)&Bfz[(size_t)((k8 * (BN / 8) + tn) * 32 + lane) * 2];
        }
#pragma unroll
        for (int i = 0; i < 2; i++)
#pragma unroll
            for (int j = 0; j < NJ; j++) mma_tf32(acc[i][j], a[i], b[j]);
    }

    int g = lane >> 2, tg = lane & 3;

    if (NORM) {
        if (tid < BM) rowss[tid] = 0.f;
        __syncthreads();
        float ss0[2] = {0.f, 0.f}, ss1[2] = {0.f, 0.f};
#pragma unroll
        for (int i = 0; i < 2; i++)
#pragma unroll
            for (int j = 0; j < NJ; j++) {
                int c = (wn * NJ + j) * 8 + tg * 2;
                float2 bb = *(const float2*)&biasz[c];
                float vx = acc[i][j].x + bb.x, vy = acc[i][j].y + bb.y;
                float vz = acc[i][j].z + bb.x, vw = acc[i][j].w + bb.y;
                ss0[i] += vx * vx + vy * vy;
                ss1[i] += vz * vz + vw * vw;
            }
#pragma unroll
        for (int i = 0; i < 2; i++) {
            atomicAdd(&rowss[wm * 32 + i * 16 + g], ss0[i]);
            atomicAdd(&rowss[wm * 32 + i * 16 + g + 8], ss1[i]);
        }
        __syncthreads();
    }

#pragma unroll
    for (int i = 0; i < 2; i++) {
        int r0 = m0 + wm * 32 + i * 16 + g;
        float s0 = 1.0f, s1 = 1.0f;
        if (NORM) {
            s0 = 1.0f / fmaxf(sqrtf(rowss[wm * 32 + i * 16 + g]), 1e-12f);
            s1 = 1.0f / fmaxf(sqrtf(rowss[wm * 32 + i * 16 + g + 8]), 1e-12f);
        }
#pragma unroll
        for (int j = 0; j < NJ; j++) {
            int c = (wn * NJ + j) * 8 + tg * 2;
            float bx = 0.f, by = 0.f;
            if (BIAS) { float2 bb = *(const float2*)&biasz[c]; bx = bb.x; by = bb.y; }
            float2 v01 = make_float2(acc[i][j].x + bx, acc[i][j].y + by);
            float2 v23 = make_float2(acc[i][j].z + bx, acc[i][j].w + by);
            if (LRELU) {
                v01.x = lrelu(v01.x); v01.y = lrelu(v01.y);
                v23.x = lrelu(v23.x); v23.y = lrelu(v23.y);
            }
            if (NORM) {
                v01.x *= s0; v01.y *= s0;
                v23.x *= s1; v23.y *= s1;
            }
            if (r0 < M)     *(float2*)&Cz[(size_t)r0 * ldc + c] = v01;
            if (r0 + 8 < M) *(float2*)&Cz[(size_t)(r0 + 8) * ldc + c] = v23;
        }
    }
}

// ---- batched dual GEMM, B fragments from gmem (BK=32 loop; full-K staging
// would need 128KB/block -> 1 block/SM, the known R6/R12 failure) ----
template <int K>
__global__ __launch_bounds__(256, 2) void dual_gemm_tc_b(
    const float* __restrict__ A1, size_t sA1,
    const uint32_t* __restrict__ B1f, size_t sB1, const float* __restrict__ b1, size_t sb1,
    const float* __restrict__ A2, size_t sA2,
    const uint32_t* __restrict__ B2f, size_t sB2, const float* __restrict__ b2, size_t sb2,
    const float* __restrict__ idemb, float* __restrict__ out, size_t sOut, int M) {
    const int BM = 128, BK = 32, BN = 64;
    __shared__ __align__(16) uint32_t As1[BM * BK];
    __shared__ __align__(16) uint32_t As2[BM * BK];
    int z = blockIdx.z;
    const float* A1z = A1 + (size_t)z * sA1;
    const float* A2z = A2 + (size_t)z * sA2;
    const uint32_t* B1z = B1f + (size_t)z * sB1;
    const uint32_t* B2z = B2f + (size_t)z * sB2;
    const float* b1z = b1 + (size_t)z * sb1;
    const float* b2z = b2 + (size_t)z * sb2;
    float* outz = out + (size_t)z * sOut;

    int tid = threadIdx.x, lane = tid & 31, w = tid >> 5;
    int wm = w >> 1, wn = w & 1;
    int m0 = blockIdx.x * BM;

    float4 acc1[2][4], acc2[2][4];
#pragma unroll
    for (int i = 0; i < 2; i++)
#pragma unroll
        for (int j = 0; j < 4; j++) {
            acc1[i][j] = make_float4(0.f, 0.f, 0.f, 0.f);
            acc2[i][j] = make_float4(0.f, 0.f, 0.f, 0.f);
        }

    for (int k0 = 0; k0 < K; k0 += BK) {
        fill_A<BM, BK>(As1, A1z, m0, M, K, k0);
        fill_A<BM, BK>(As2, A2z, m0, M, K, k0);
        __syncthreads();
#pragma unroll
        for (int k8 = 0; k8 < BK / 8; k8++) {
            int k8g = (k0 >> 3) + k8;
            uint32_t a1[2][4], a2[2][4], bf1[4][2], bf2[4][2];
#pragma unroll
            for (int i = 0; i < 2; i++) {
                int tm = wm * 2 + i;
                *(uint4*)a1[i] = *(const uint4*)&As1[(size_t)((k8 * (BM / 16) + tm) * 32 + (lane ^ k8)) * 4];
                *(uint4*)a2[i] = *(const uint4*)&As2[(size_t)((k8 * (BM / 16) + tm) * 32 + (lane ^ k8)) * 4];
            }
#pragma unroll
            for (int j = 0; j < 4; j++) {
                int tn = wn * 4 + j;
                *(uint2*)bf1[j] = *(const uint2*)&B1z[(size_t)((k8g * 8 + tn) * 32 + lane) * 2];
                *(uint2*)bf2[j] = *(const uint2*)&B2z[(size_t)((k8g * 8 + tn) * 32 + lane) * 2];
            }
#pragma unroll
            for (int i = 0; i < 2; i++)
#pragma unroll
                for (int j = 0; j < 4; j++) {
                    mma_tf32(acc1[i][j], a1[i], bf1[j]);
                    mma_tf32(acc2[i][j], a2[i], bf2[j]);
                }
        }
        __syncthreads();
    }

    int g = lane >> 2, tg = lane & 3;
#pragma unroll
    for (int i = 0; i < 2; i++) {
        int r0 = m0 + wm * 32 + i * 16 + g;
#pragma unroll
        for (int j = 0; j < 4; j++) {
            int c = wn * 32 + j * 8 + tg * 2;
            float2 bb1 = *(const float2*)&b1z[c];
            float2 bb2 = *(const float2*)&b2z[c];
            if (r0 < M) {
                float2 idv = *(const float2*)&idemb[(size_t)r0 * D_X + c];
                float u1 = lrelu(acc1[i][j].x + bb1.x);
                float u2 = lrelu(acc1[i][j].y + bb1.y);
                float o1 = lrelu(acc2[i][j].x + bb2.x + u1 + idv.x);
                float o2 = lrelu(acc2[i][j].y + bb2.y + u2 + idv.y);
                *(float2*)&outz[(size_t)r0 * D_X + c] = make_float2(o1, o2);
            }
            if (r0 + 8 < M) {
                float2 idv = *(const float2*)&idemb[(size_t)(r0 + 8) * D_X + c];
                float u1 = lrelu(acc1[i][j].z + bb1.x);
                float u2 = lrelu(acc1[i][j].w + bb1.y);
                float o1 = lrelu(acc2[i][j].z + bb2.x + u1 + idv.x);
                float o2 = lrelu(acc2[i][j].w + bb2.y + u2 + idv.y);
                *(float2*)&outz[(size_t)(r0 + 8) * D_X + c] = make_float2(o1, o2);
            }
        }
    }
}

// ---------------- CSR build ----------------
// merged: zero cursor (deg) + words row_ptr in one launch
__global__ void init_misc(int* __restrict__ cursor, const int* __restrict__ words, int W,
                          int* __restrict__ wrp) {
    int i = blockIdx.x * blockDim.x + threadIdx.x;
    if (i < N_NODES + 1) cursor[i] = 0;
    if (i < W) {
        int it = words[i];
        int prev = (i == 0) ? -1 : words[i - 1];
        for (int t = prev + 1; t <= it; t++) wrp[t] = i;
        if (i == W - 1)
            for (int t = it + 1; t <= I_NODES; t++) wrp[t] = W;
    }
}

__global__ void deg_hist(const int* __restrict__ ei, int E, int* __restrict__ deg) {
    int e = blockIdx.x * blockDim.x + threadIdx.x;
    if (e < E) atomicAdd(&deg[ei[E + e]], 1);
}

__global__ void deg_partials(const int* __restrict__ deg, int* __restrict__ bsum, int n) {
    __shared__ int s[256];
    int i = blockIdx.x * 256 + threadIdx.x;
    s[threadIdx.x] = (i < n) ? deg[i] : 0;
    __syncthreads();
    for (int o = 128; o > 0; o >>= 1) {
        if (threadIdx.x < o) s[threadIdx.x] += s[threadIdx.x + o];
        __syncthreads();
    }
    if (threadIdx.x == 0) bsum[blockIdx.x] = s[0];
}

__global__ void deg_scan(const int* __restrict__ deg, const int* __restrict__ bsum,
                         int* __restrict__ rp, int* __restrict__ cursor, int n) {
    __shared__ int s[256];
    __shared__ int off_s;
    int b = blockIdx.x, t = threadIdx.x;
    if (t == 0) {
        int o = 0;
        for (int k = 0; k < b; k++) o += bsum[k];
        off_s = o;
    }
    int i = b * 256 + t;
    int v = (i < n) ? deg[i] : 0;
    s[t] = v;
    __syncthreads();
    for (int o = 1; o < 256; o <<= 1) {
        int add = (t >= o) ? s[t - o] : 0;
        __syncthreads();
        s[t] += add;
        __syncthreads();
    }
    int ex = s[t] - v + off_s;
    if (i < n) { rp[i] = ex; cursor[i] = ex; }
    if (i == n - 1) rp[n] = ex + v;
}

// merged: csr_fill (y==0) + user-row normalize (y==1..3, z = y-1)
__global__ void csr_fill_norm(const int* __restrict__ ei, int E,
                              int* __restrict__ cursor, int* __restrict__ col,
                              const float* __restrict__ pref, float* __restrict__ xbase) {
    if (blockIdx.y == 0) {
        int e = blockIdx.x * blockDim.x + threadIdx.x;
        if (e >= E) return;
        int s = ei[e], d = ei[E + e];
        int pos = atomicAdd(&cursor[d], 1);
        col[pos] = s;
    } else {
        int row = (int)(((long)blockIdx.x * blockDim.x + threadIdx.x) >> 5);
        int lane = threadIdx.x & 31;
        if (row >= U_NODES) return;
        int z = blockIdx.y - 1;
        float* x = xbase + (size_t)z * SZ_X;
        const float* pref_m = pref + (size_t)z * U_NODES * D_LAT;
        float4 v = ((const float4*)(pref_m + (size_t)row * D_LAT))[lane];
        float ss = v.x * v.x + v.y * v.y + v.z * v.z + v.w * v.w;
        ss = warp_sum(ss);
        float s = 1.0f / fmaxf(sqrtf(ss), 1e-12f);
        v.x *= s; v.y *= s; v.z *= s; v.w *= s;
        ((float4*)(x + (size_t)row * D_LAT))[lane] = v;
    }
}

// ---------------- gathers (4-wide, modality-batched via grid.y) ----------------
__global__ void words_gather(const int* __restrict__ rp, const int* __restrict__ words,
                             int W, const float* __restrict__ word_emb,
                             float* __restrict__ tfeat) {
    int it = (int)(((long)blockIdx.x * blockDim.x + threadIdx.x) >> 5);
    int lane = threadIdx.x & 31;
    if (it >= I_NODES) return;
    int beg = rp[it], end = rp[it + 1];
    float4 a = make_float4(0.f, 0.f, 0.f, 0.f);
    int j = beg;
    for (; j + 4 <= end; j += 4) {
        int w0 = words[W + j], w1 = words[W + j + 1], w2 = words[W + j + 2], w3 = words[W + j + 3];
        acc4(a, ((const float4*)(word_emb + (size_t)w0 * D_LAT))[lane]);
        acc4(a, ((const float4*)(word_emb + (size_t)w1 * D_LAT))[lane]);
        acc4(a, ((const float4*)(word_emb + (size_t)w2 * D_LAT))[lane]);
        acc4(a, ((const float4*)(word_emb + (size_t)w3 * D_LAT))[lane]);
    }
    for (; j < end; j++)
        acc4(a, ((const float4*)(word_emb + (size_t)words[W + j] * D_LAT))[lane]);
    float inv = 1.0f / (float)max(end - beg, 1);
    a.x *= inv; a.y *= inv; a.z *= inv; a.w *= inv;
    ((float4*)(tfeat + (size_t)it * D_LAT))[lane] = a;
}

__global__ void gather128_b(const int* __restrict__ rp, const int* __restrict__ col,
                            const float* __restrict__ xbase, float* __restrict__ aggbase) {
    int n = (int)(((long)blockIdx.x * blockDim.x + threadIdx.x) >> 5);
    int lane = threadIdx.x & 31;
    if (n >= N_NODES) return;
    int z = blockIdx.y;
    const float* x = xbase + (size_t)z * SZ_X;
    float* agg = aggbase + (size_t)z * SZ_X;
    int beg = rp[n], end = rp[n + 1];
    float4 a = make_float4(0.f, 0.f, 0.f, 0.f);
    int j = beg;
    for (; j + 4 <= end; j += 4) {
        int s0 = col[j], s1 = col[j + 1], s2 = col[j + 2], s3 = col[j + 3];
        acc4(a, ((const float4*)(x + (size_t)s0 * D_LAT))[lane]);
        acc4(a, ((const float4*)(x + (size_t)s1 * D_LAT))[lane]);
        acc4(a, ((const float4*)(x + (size_t)s2 * D_LAT))[lane]);
        acc4(a, ((const float4*)(x + (size_t)s3 * D_LAT))[lane]);
    }
    for (; j < end; j++)
        acc4(a, ((const float4*)(x + (size_t)col[j] * D_LAT))[lane]);
    ((float4*)(agg + (size_t)n * D_LAT))[lane] = a;
}

__global__ void gather64_b(const int* __restrict__ rp, const int* __restrict__ col,
                           const float* __restrict__ xbase, float* __restrict__ aggbase) {
    int n = (int)(((long)blockIdx.x * blockDim.x + threadIdx.x) >> 5);
    int lane = threadIdx.x & 31;
    if (n >= N_NODES) return;
    int z = blockIdx.y;
    const float* x = xbase + (size_t)z * SZ_X64;
    float* agg = aggbase + (size_t)z * SZ_X64;
    int beg = rp[n], end = rp[n + 1];
    float2 a = make_float2(0.f, 0.f);
    int j = beg;
    for (; j + 4 <= end; j += 4) {
        int s0 = col[j], s1 = col[j + 1], s2 = col[j + 2], s3 = col[j + 3];
        acc2(a, ((const float2*)(x + (size_t)s0 * D_X))[lane]);
        acc2(a, ((const float2*)(x + (size_t)s1 * D_X))[lane]);
        acc2(a, ((const float2*)(x + (size_t)s2 * D_X))[lane]);
        acc2(a, ((const float2*)(x + (size_t)s3 * D_X))[lane]);
    }
    for (; j < end; j++)
        acc2(a, ((const float2*)(x + (size_t)col[j] * D_X))[lane]);
    ((float2*)(agg + (size_t)n * D_X))[lane] = a;
}

// ---------------- final scoring ----------------
__global__ void final_kernel(const float* __restrict__ rep,
                             const int* __restrict__ users, const int* __restrict__ pos,
                             const int* __restrict__ neg, float* __restrict__ out, int Bn) {
    int gw = (int)(((long)blockIdx.x * blockDim.x + threadIdx.x) >> 5);
    int lane = threadIdx.x & 31;
    if (gw >= Bn) return;
    int u = users[gw], p = pos[gw], n = neg[gw];
    const size_t stride = (size_t)N_NODES * D_X;
    const float* r0 = rep;
    const float* r1 = rep + stride;
    const float* r2 = rep + 2 * stride;

    auto ld = [&](const float* base, int node) {
        return ((const float2*)(base + (size_t)node * D_X))[lane];
    };
    float2 t_u = ld(r2, u), t_p = ld(r2, p), t_n = ld(r2, n);
    float2 a_u = ld(r0, u), b_u = ld(r1, u);
    float2 a_p = ld(r0, p), b_p = ld(r1, p);
    float2 a_n = ld(r0, n), b_n = ld(r1, n);

    const float third = 1.0f / 3.0f;
    float2 pu = make_float2((a_u.x + b_u.x + t_u.x) * third, (a_u.y + b_u.y + t_u.y) * third);
    float2 pp = make_float2((a_p.x + b_p.x + t_p.x) * third, (a_p.y + b_p.y + t_p.y) * third);
    float2 pn = make_float2((a_n.x + b_n.x + t_n.x) * third, (a_n.y + b_n.y + t_n.y) * third);

    float prep  = t_u.x * t_p.x + t_u.y * t_p.y;
    float pren  = t_u.x * t_n.x + t_u.y * t_n.y;
    float postp = pu.x * pp.x + pu.y * pp.y;
    float postn = pu.x * pn.x + pu.y * pn.y;

    prep = warp_sum(prep);
    pren = warp_sum(pren);
    postp = warp_sum(postp);
    postn = warp_sum(postn);

    if (lane == 0) {
        float sp = 1.0f / (1.0f + expf(-prep));
        float sn = 1.0f / (1.0f + expf(-pren));
        out[gw]          = postp * sp;
        out[Bn + gw]     = postn * sn;
        out[2 * Bn + gw] = prep;
        out[3 * Bn + gw] = pren;
    }
}

// ---------------- host orchestration ----------------
static inline int nblk(long n, int t) { return (int)((n + t - 1) / t); }

extern "C" void kernel_launch(void* const* d_in, const int* in_sizes, int n_in,
                              void* d_out, int out_size) {
    const float* v_feat   = (const float*)d_in[0];
    const float* a_feat   = (const float*)d_in[1];
    const float* word_emb = (const float*)d_in[2];
    const float* id_emb   = (const float*)d_in[3];
    const float* pref     = (const float*)d_in[4];
    const float* mlp_w    = (const float*)d_in[5];
    const float* mlp_b    = (const float*)d_in[6];
    const float* conv1_w  = (const float*)d_in[7];
    const float* lin1_w   = (const float*)d_in[8];
    const float* lin1_b   = (const float*)d_in[9];
    const float* g1_w     = (const float*)d_in[10];
    const float* g1_b     = (const float*)d_in[11];
    const float* conv2_w  = (const float*)d_in[12];
    const float* lin2_w   = (const float*)d_in[13];
    const float* lin2_b   = (const float*)d_in[14];
    const float* g2_w     = (const float*)d_in[15];
    const float* g2_b     = (const float*)d_in[16];
    const int*   edges    = (const int*)d_in[17];
    const int*   words    = (const int*)d_in[18];
    const int*   users    = (const int*)d_in[19];
    const int*   posn     = (const int*)d_in[20];
    const int*   negn     = (const int*)d_in[21];

    const int E  = in_sizes[17] / 2;   // 500000
    const int W  = in_sizes[18] / 2;   // 600000
    const int Bn = in_sizes[19];       // 2048

    float* sc = nullptr;
    cudaGetSymbolAddress((void**)&sc, g_scratch);

    float* tfeat = sc + OFF_TFEAT;
    float* x     = sc + R_X;                       // stride SZ_X
    float* rep   = sc + R_X;                       // stride SZ_X64 (x dead at dual2)
    float* agg   = sc + R_AGG;                     // stride SZ_X
    float* h     = sc + R_H;                       // stride SZ_X; reused as h64
    float* x64   = sc + R_AGG;                     // stride SZ_X64 (agg dead after conv1)
    float* agg64 = sc + R_AGG + 3 * SZ_X64;        // stride SZ_X64

    int* ib     = (int*)(sc + OFF_CSR);
    int* cursor = ib + ICUR;
    int* rp     = ib + IRP;
    int* bsum   = ib + IBSUM;
    int* col    = ib + ICOL;
    int* wrp    = ib + IWRP;
    uint32_t* wf = (uint32_t*)(sc + OFF_WF);

    const int NB = nblk(N_NODES, 256);

    // dynamic smem opt-in for K=128 full-staging GEMMs (host attr; once)
    static bool attr_done = false;
    if (!attr_done) {
        cudaFuncSetAttribute((const void*)gemm_tc_f<128, 128, true, false, true>,
                             cudaFuncAttributeMaxDynamicSharedMemorySize, 65536);
        cudaFuncSetAttribute((const void*)gemm_tc_f<128, 128, false, true, false>,
                             cudaFuncAttributeMaxDynamicSharedMemorySize, 65536);
        attr_done = true;
    }

    // 0: weight fragments (tf32, fragment order)
    prep_weights<<<nblk(WF_TOTAL, 256), 256>>>(mlp_w, lin1_w, g1_w, lin2_w, g2_w,
                                               conv1_w, conv2_w, wf);
    // 1: zero cursor + words row_ptr (merged)
    init_misc<<<nblk(W, 256), 256>>>(cursor, words, W, wrp);
    // 2: t_feat gather-mean
    words_gather<<<nblk((long)I_NODES * 32, 256), 256>>>(wrp, words, W, word_emb, tfeat);
    // 3: mlp GEMM + fused item-row normalize  <-- ncu capture target
    {
        dim3 grid(nblk(I_NODES, 128), 1, 3);
        gemm_tc_f<128, 128, true, false, true><<<grid, 256, 65536>>>(
            v_feat, a_feat, tfeat,
            wf + WF_MLP, 128 * 128, mlp_b, 128,
            x + (size_t)U_NODES * D_LAT, SZ_X, I_NODES, 128);
    }
    // 4-6: CSR histogram + scan
    deg_hist<<<nblk(E, 256), 256>>>(edges, E, cursor);
    deg_partials<<<NB, 256>>>(cursor, bsum, N_NODES);
    deg_scan<<<NB, 256>>>(cursor, bsum, rp, cursor, N_NODES);
    // 7: csr_fill + user-row normalize (merged)
    {
        dim3 grid(nblk((long)U_NODES * 32, 256), 4);
        csr_fill_norm<<<grid, 256>>>(edges, E, cursor, col, pref, x);
    }
    // 8: layer-1 gather
    {
        dim3 grid(nblk((long)N_NODES * 32, 256), 3);
        gather128_b<<<grid, 256>>>(rp, col, x, agg);
    }
    // 9: conv1 (full-K staging)
    {
        dim3 grid(nblk(N_NODES, 128), 1, 3);
        gemm_tc_f<128, 128, false, true, false><<<grid, 256, 65536>>>(
            agg, agg + SZ_X, agg + 2 * SZ_X,
            wf + WF_C1, 128 * 128, nullptr, 0,
            h, SZ_X, N_NODES, 128);
    }
    // 10: dual1 -> x64 (into R_AGG; agg dead)
    {
        dim3 grid(nblk(N_NODES, 128), 1, 3);
        dual_gemm_tc_b<128><<<grid, 256>>>(
            x, SZ_X, wf + WF_LIN1, 128 * 64, lin1_b, 64,
            h, SZ_X, wf + WF_G1, 128 * 64, g1_b, 64,
            id_emb, x64, SZ_X64, N_NODES);
    }
    // 11: layer-2 gather
    {
        dim3 grid(nblk((long)N_NODES * 32, 256), 3);
        gather64_b<<<grid, 256>>>(rp, col, x64, agg64);
    }
    // 12: conv2 -> h64 (full-K staging, 32KB dynamic, under default limit)
    {
        dim3 grid(nblk(N_NODES, 128), 1, 3);
        gemm_tc_f<64, 64, false, true, false><<<grid, 256, 32768>>>(
            agg64, agg64 + SZ_X64, agg64 + 2 * SZ_X64,
            wf + WF_C2, 64 * 64, nullptr, 0,
            h, SZ_X64, N_NODES, 64);
    }
    // 13: dual2 -> rep (into R_X; x dead)
    {
        dim3 grid(nblk(N_NODES, 128), 1, 3);
        dual_gemm_tc_b<64><<<grid, 256>>>(
            x64, SZ_X64, wf + WF_LIN2, 64 * 64, lin2_b, 64,
            h, SZ_X64, wf + WF_G2, 64 * 64, g2_b, 64,
            id_emb, rep, SZ_X64, N_NODES);
    }
    // 14: final scoring
    final_kernel<<<nblk((long)Bn * 32, 256), 256>>>(rep, users, posn, negn,
                                                    (float*)d_out, Bn);
}

// round 17
// speedup vs baseline: 1.0586x; 1.0251x over previous
#include <cuda_runtime.h>
#include <cuda_bf16.h>
#include <math.h>
#include <stdint.h>

// ---------------- problem constants ----------------
#define U_NODES 40000
#define I_NODES 30000
#define N_NODES 70000
#define D_LAT   128
#define D_X     64

// ---------------- scratch layout (floats) ----------------
static const size_t SZ_X     = (size_t)N_NODES * D_LAT;      // 8,960,000
static const size_t SZ_X64   = (size_t)N_NODES * D_X;        // 4,480,000

static const size_t OFF_TFEAT = 0;                     // I*128
static const size_t R_X   = 4000000;                   // x -> rep
static const size_t R_AGG = R_X + 3 * SZ_X;            // agg128 -> x64 + agg64
static const size_t R_H   = R_AGG + 3 * SZ_X;          // h -> h64
static const size_t OFF_CSR = R_H + 3 * SZ_X;          // int scratch
static const size_t OFF_WF  = OFF_CSR + 700000;        // tf32 weight fragments
static const size_t SCRATCH_TOTAL = OFF_WF + 190000;

__device__ float g_scratch[SCRATCH_TOTAL];

// int-scratch offsets (ints within OFF_CSR)
#define ICUR  0
#define IRP   70016
#define IBSUM 140032
#define ICOL  140320
#define IWRP  640320

// weight-fragment offsets (words within OFF_WF)
#define WF_MLP  0
#define WF_LIN1 49152
#define WF_G1   73728
#define WF_LIN2 98304
#define WF_G2   110592
#define WF_C1   122880
#define WF_C2   172032
#define WF_TOTAL 184320

// ---------------- helpers ----------------
__device__ __forceinline__ float lrelu(float v) { return v >= 0.0f ? v : 0.01f * v; }

__device__ __forceinline__ float warp_sum(float v) {
#pragma unroll
    for (int o = 16; o > 0; o >>= 1) v += __shfl_xor_sync(0xFFFFFFFFu, v, o);
    return v;
}

__device__ __forceinline__ uint32_t f2tf(float f) {
    uint32_t r;
    asm("cvt.rna.tf32.f32 %0, %1;" : "=r"(r) : "f"(f));
    return r;
}

__device__ __forceinline__ void mma_tf32(float4& d, const uint32_t* a, const uint32_t* b) {
    asm volatile(
        "mma.sync.aligned.m16n8k8.row.col.f32.tf32.tf32.f32 "
        "{%0,%1,%2,%3}, {%4,%5,%6,%7}, {%8,%9}, {%0,%1,%2,%3};"
        : "+f"(d.x), "+f"(d.y), "+f"(d.z), "+f"(d.w)
        : "r"(a[0]), "r"(a[1]), "r"(a[2]), "r"(a[3]), "r"(b[0]), "r"(b[1]));
}

__device__ __forceinline__ void acc4(float4& a, float4 v) {
    a.x += v.x; a.y += v.y; a.z += v.z; a.w += v.w;
}
__device__ __forceinline__ void acc2(float2& a, float2 v) { a.x += v.x; a.y += v.y; }

// ---- A smem tile fill (fragment-order layout + k8 lane swizzle) ----
template <int BM, int BK>
__device__ __forceinline__ void fill_A(uint32_t* As, const float* __restrict__ A,
                                       int m0, int M, int lda, int k0) {
    const int NF4 = BM * BK / 4 / 256;
    int tid = threadIdx.x;
#pragma unroll
    for (int p = 0; p < NF4; p++) {
        int f = tid + p * 256;
        int m = f / (BK / 4);
        int k4 = f % (BK / 4);
        int gm = m0 + m;
        float4 v = make_float4(0.f, 0.f, 0.f, 0.f);
        if (gm < M) v = *(const float4*)&A[(size_t)gm * lda + k0 + k4 * 4];
        int k8 = k4 >> 1;
        int tm = m >> 4;
        int lane_base = (m & 7) * 4;
        int reg = (((m & 15) >= 8) ? 1 : 0) + ((k4 & 1) ? 2 : 0);
        uint32_t* blk = As + (size_t)((k8 * (BM / 16) + tm) * 32) * 4 + reg;
        blk[((lane_base + 0) ^ k8) * 4] = f2tf(v.x);
        blk[((lane_base + 1) ^ k8) * 4] = f2tf(v.y);
        blk[((lane_base + 2) ^ k8) * 4] = f2tf(v.z);
        blk[((lane_base + 3) ^ k8) * 4] = f2tf(v.w);
    }
}

// ---------- weight prep: write tf32 fragments for the full K range ----------
__global__ void prep_weights(const float* __restrict__ mlp_w, const float* __restrict__ lin1_w,
                             const float* __restrict__ g1_w, const float* __restrict__ lin2_w,
                             const float* __restrict__ g2_w, const float* __restrict__ conv1_w,
                             const float* __restrict__ conv2_w, uint32_t* __restrict__ wf) {
    int i = blockIdx.x * blockDim.x + threadIdx.x;
    if (i >= WF_TOTAL) return;
    const float* src; int K, N, rel; bool tr;
    if (i < WF_LIN1)      { src = mlp_w;  K = 128; N = 128; tr = true;  rel = i; }
    else if (i < WF_G1)   { src = lin1_w; K = 128; N = 64;  tr = true;  rel = i - WF_LIN1; }
    else if (i < WF_LIN2) { src = g1_w;   K = 128; N = 64;  tr = true;  rel = i - WF_G1; }
    else if (i < WF_G2)   { src = lin2_w; K = 64;  N = 64;  tr = true;  rel = i - WF_LIN2; }
    else if (i < WF_C1)   { src = g2_w;   K = 64;  N = 64;  tr = true;  rel = i - WF_G2; }
    else if (i < WF_C2)   { src = conv1_w; K = 128; N = 128; tr = false; rel = i - WF_C1; }
    else                  { src = conv2_w; K = 64;  N = 64;  tr = false; rel = i - WF_C2; }
    int perz = K * N;
    int z = rel / perz, w = rel % perz;
    int reg = w & 1, q = w >> 1, lane = q & 31, idx = q >> 5;
    int tn = idx % (N / 8), k8 = idx / (N / 8);
    int n = tn * 8 + (lane >> 2);
    int k = k8 * 8 + (lane & 3) + reg * 4;
    float v = tr ? src[((size_t)z * N + n) * K + k]
                 : src[((size_t)z * K + k) * N + n];
    wf[i] = f2tf(v);
}

// ---------- batched TC GEMM, FULL-K A staging: BM=128, one sync total ----------
template <int K, int BN, bool BIAS, bool LRELU, bool NORM>
__global__ __launch_bounds__(256, 2) void gemm_tc_f(
    const float* __restrict__ Aa, const float* __restrict__ Ab, const float* __restrict__ Ac,
    const uint32_t* __restrict__ Bf, size_t sBf,
    const float* __restrict__ bias, size_t sbias,
    float* __restrict__ C, size_t sC, int M, int ldc) {
    const int BM = 128;
    const int NJ = BN / 16;
    extern __shared__ uint32_t As[];           // BM * K words
    __shared__ float rowss[BM];
    int z = blockIdx.z;
    const float* A = (z == 0) ? Aa : (z == 1) ? Ab : Ac;
    const uint32_t* Bfz = Bf + (size_t)z * sBf;
    const float* biasz = BIAS ? bias + (size_t)z * sbias : nullptr;
    float* Cz = C + (size_t)z * sC;

    int tid = threadIdx.x, lane = tid & 31, w = tid >> 5;
    int wm = w & 3, wn = w >> 2;
    int m0 = blockIdx.x * BM;

    float4 acc[2][NJ];
#pragma unroll
    for (int i = 0; i < 2; i++)
#pragma unroll
        for (int j = 0; j < NJ; j++) acc[i][j] = make_float4(0.f, 0.f, 0.f, 0.f);

    fill_A<BM, K>(As, A, m0, M, K, 0);
    __syncthreads();

#pragma unroll
    for (int k8 = 0; k8 < K / 8; k8++) {
        uint32_t a[2][4], b[NJ][2];
#pragma unroll
        for (int i = 0; i < 2; i++) {
            int tm = wm * 2 + i;
            *(uint4*)a[i] = *(const uint4*)&As[(size_t)((k8 * (BM / 16) + tm) * 32 + (lane ^ k8)) * 4];
        }
#pragma unroll
        for (int j = 0; j < NJ; j++) {
            int tn = wn * NJ + j;
            *(uint2*)b[j] = *(const uint2*)&Bfz[(size_t)((k8 * (BN / 8) + tn) * 32 + lane) * 2];
        }
#pragma unroll
        for (int i = 0; i < 2; i++)
#pragma unroll
            for (int j = 0; j < NJ; j++) mma_tf32(acc[i][j], a[i], b[j]);
    }

    int g = lane >> 2, tg = lane & 3;

    if (NORM) {
        if (tid < BM) rowss[tid] = 0.f;
        __syncthreads();
        float ss0[2] = {0.f, 0.f}, ss1[2] = {0.f, 0.f};
#pragma unroll
        for (int i = 0; i < 2; i++)
#pragma unroll
            for (int j = 0; j < NJ; j++) {
                int c = (wn * NJ + j) * 8 + tg * 2;
                float2 bb = *(const float2*)&biasz[c];
                float vx = acc[i][j].x + bb.x, vy = acc[i][j].y + bb.y;
                float vz = acc[i][j].z + bb.x, vw = acc[i][j].w + bb.y;
                ss0[i] += vx * vx + vy * vy;
                ss1[i] += vz * vz + vw * vw;
            }
#pragma unroll
        for (int i = 0; i < 2; i++) {
            atomicAdd(&rowss[wm * 32 + i * 16 + g], ss0[i]);
            atomicAdd(&rowss[wm * 32 + i * 16 + g + 8], ss1[i]);
        }
        __syncthreads();
    }

#pragma unroll
    for (int i = 0; i < 2; i++) {
        int r0 = m0 + wm * 32 + i * 16 + g;
        float s0 = 1.0f, s1 = 1.0f;
        if (NORM) {
            s0 = 1.0f / fmaxf(sqrtf(rowss[wm * 32 + i * 16 + g]), 1e-12f);
            s1 = 1.0f / fmaxf(sqrtf(rowss[wm * 32 + i * 16 + g + 8]), 1e-12f);
        }
#pragma unroll
        for (int j = 0; j < NJ; j++) {
            int c = (wn * NJ + j) * 8 + tg * 2;
            float bx = 0.f, by = 0.f;
            if (BIAS) { float2 bb = *(const float2*)&biasz[c]; bx = bb.x; by = bb.y; }
            float2 v01 = make_float2(acc[i][j].x + bx, acc[i][j].y + by);
            float2 v23 = make_float2(acc[i][j].z + bx, acc[i][j].w + by);
            if (LRELU) {
                v01.x = lrelu(v01.x); v01.y = lrelu(v01.y);
                v23.x = lrelu(v23.x); v23.y = lrelu(v23.y);
            }
            if (NORM) {
                v01.x *= s0; v01.y *= s0;
                v23.x *= s1; v23.y *= s1;
            }
            if (r0 < M)     *(float2*)&Cz[(size_t)r0 * ldc + c] = v01;
            if (r0 + 8 < M) *(float2*)&Cz[(size_t)(r0 + 8) * ldc + c] = v23;
        }
    }
}

// ---- batched dual GEMM, FULL-K sequential A staging through ONE buffer ----
// smem = BM*K words (64KB for K=128, 32KB for K=64) -> 2 blocks/SM kept.
template <int K>
__global__ __launch_bounds__(256, 2) void dual_gemm_tc_f(
    const float* __restrict__ A1, size_t sA1,
    const uint32_t* __restrict__ B1f, size_t sB1, const float* __restrict__ b1, size_t sb1,
    const float* __restrict__ A2, size_t sA2,
    const uint32_t* __restrict__ B2f, size_t sB2, const float* __restrict__ b2, size_t sb2,
    const float* __restrict__ idemb, float* __restrict__ out, size_t sOut, int M) {
    const int BM = 128, BN = 64;
    extern __shared__ uint32_t As[];           // BM * K words
    int z = blockIdx.z;
    const float* A1z = A1 + (size_t)z * sA1;
    const float* A2z = A2 + (size_t)z * sA2;
    const uint32_t* B1z = B1f + (size_t)z * sB1;
    const uint32_t* B2z = B2f + (size_t)z * sB2;
    const float* b1z = b1 + (size_t)z * sb1;
    const float* b2z = b2 + (size_t)z * sb2;
    float* outz = out + (size_t)z * sOut;

    int tid = threadIdx.x, lane = tid & 31, w = tid >> 5;
    int wm = w >> 1, wn = w & 1;
    int m0 = blockIdx.x * BM;

    float4 acc1[2][4], acc2[2][4];
#pragma unroll
    for (int i = 0; i < 2; i++)
#pragma unroll
        for (int j = 0; j < 4; j++) {
            acc1[i][j] = make_float4(0.f, 0.f, 0.f, 0.f);
            acc2[i][j] = make_float4(0.f, 0.f, 0.f, 0.f);
        }

    // ---- GEMM 1: acc1 = A1 @ B1 ----
    fill_A<BM, K>(As, A1z, m0, M, K, 0);
    __syncthreads();
#pragma unroll
    for (int k8 = 0; k8 < K / 8; k8++) {
        uint32_t a[2][4], b[4][2];
#pragma unroll
        for (int i = 0; i < 2; i++) {
            int tm = wm * 2 + i;
            *(uint4*)a[i] = *(const uint4*)&As[(size_t)((k8 * (BM / 16) + tm) * 32 + (lane ^ k8)) * 4];
        }
#pragma unroll
        for (int j = 0; j < 4; j++) {
            int tn = wn * 4 + j;
            *(uint2*)b[j] = *(const uint2*)&B1z[(size_t)((k8 * 8 + tn) * 32 + lane) * 2];
        }
#pragma unroll
        for (int i = 0; i < 2; i++)
#pragma unroll
            for (int j = 0; j < 4; j++) mma_tf32(acc1[i][j], a[i], b[j]);
    }
    __syncthreads();

    // ---- GEMM 2: acc2 = A2 @ B2 (reuse buffer) ----
    fill_A<BM, K>(As, A2z, m0, M, K, 0);
    __syncthreads();
#pragma unroll
    for (int k8 = 0; k8 < K / 8; k8++) {
        uint32_t a[2][4], b[4][2];
#pragma unroll
        for (int i = 0; i < 2; i++) {
            int tm = wm * 2 + i;
            *(uint4*)a[i] = *(const uint4*)&As[(size_t)((k8 * (BM / 16) + tm) * 32 + (lane ^ k8)) * 4];
        }
#pragma unroll
        for (int j = 0; j < 4; j++) {
            int tn = wn * 4 + j;
            *(uint2*)b[j] = *(const uint2*)&B2z[(size_t)((k8 * 8 + tn) * 32 + lane) * 2];
        }
#pragma unroll
        for (int i = 0; i < 2; i++)
#pragma unroll
            for (int j = 0; j < 4; j++) mma_tf32(acc2[i][j], a[i], b[j]);
    }

    int g = lane >> 2, tg = lane & 3;
#pragma unroll
    for (int i = 0; i < 2; i++) {
        int r0 = m0 + wm * 32 + i * 16 + g;
#pragma unroll
        for (int j = 0; j < 4; j++) {
            int c = wn * 32 + j * 8 + tg * 2;
            float2 bb1 = *(const float2*)&b1z[c];
            float2 bb2 = *(const float2*)&b2z[c];
            if (r0 < M) {
                float2 idv = *(const float2*)&idemb[(size_t)r0 * D_X + c];
                float u1 = lrelu(acc1[i][j].x + bb1.x);
                float u2 = lrelu(acc1[i][j].y + bb1.y);
                float o1 = lrelu(acc2[i][j].x + bb2.x + u1 + idv.x);
                float o2 = lrelu(acc2[i][j].y + bb2.y + u2 + idv.y);
                *(float2*)&outz[(size_t)r0 * D_X + c] = make_float2(o1, o2);
            }
            if (r0 + 8 < M) {
                float2 idv = *(const float2*)&idemb[(size_t)(r0 + 8) * D_X + c];
                float u1 = lrelu(acc1[i][j].z + bb1.x);
                float u2 = lrelu(acc1[i][j].w + bb1.y);
                float o1 = lrelu(acc2[i][j].z + bb2.x + u1 + idv.x);
                float o2 = lrelu(acc2[i][j].w + bb2.y + u2 + idv.y);
                *(float2*)&outz[(size_t)(r0 + 8) * D_X + c] = make_float2(o1, o2);
            }
        }
    }
}

// ---------------- CSR build ----------------
__global__ void init_misc(int* __restrict__ cursor, const int* __restrict__ words, int W,
                          int* __restrict__ wrp) {
    int i = blockIdx.x * blockDim.x + threadIdx.x;
    if (i < N_NODES + 1) cursor[i] = 0;
    if (i < W) {
        int it = words[i];
        int prev = (i == 0) ? -1 : words[i - 1];
        for (int t = prev + 1; t <= it; t++) wrp[t] = i;
        if (i == W - 1)
            for (int t = it + 1; t <= I_NODES; t++) wrp[t] = W;
    }
}

__global__ void deg_hist(const int* __restrict__ ei, int E, int* __restrict__ deg) {
    int e = blockIdx.x * blockDim.x + threadIdx.x;
    if (e < E) atomicAdd(&deg[ei[E + e]], 1);
}

__global__ void deg_partials(const int* __restrict__ deg, int* __restrict__ bsum, int n) {
    __shared__ int s[256];
    int i = blockIdx.x * 256 + threadIdx.x;
    s[threadIdx.x] = (i < n) ? deg[i] : 0;
    __syncthreads();
    for (int o = 128; o > 0; o >>= 1) {
        if (threadIdx.x < o) s[threadIdx.x] += s[threadIdx.x + o];
        __syncthreads();
    }
    if (threadIdx.x == 0) bsum[blockIdx.x] = s[0];
}

__global__ void deg_scan(const int* __restrict__ deg, const int* __restrict__ bsum,
                         int* __restrict__ rp, int* __restrict__ cursor, int n) {
    __shared__ int s[256];
    __shared__ int off_s;
    int b = blockIdx.x, t = threadIdx.x;
    if (t == 0) {
        int o = 0;
        for (int k = 0; k < b; k++) o += bsum[k];
        off_s = o;
    }
    int i = b * 256 + t;
    int v = (i < n) ? deg[i] : 0;
    s[t] = v;
    __syncthreads();
    for (int o = 1; o < 256; o <<= 1) {
        int add = (t >= o) ? s[t - o] : 0;
        __syncthreads();
        s[t] += add;
        __syncthreads();
    }
    int ex = s[t] - v + off_s;
    if (i < n) { rp[i] = ex; cursor[i] = ex; }
    if (i == n - 1) rp[n] = ex + v;
}

__global__ void csr_fill_norm(const int* __restrict__ ei, int E,
                              int* __restrict__ cursor, int* __restrict__ col,
                              const float* __restrict__ pref, float* __restrict__ xbase) {
    if (blockIdx.y == 0) {
        int e = blockIdx.x * blockDim.x + threadIdx.x;
        if (e >= E) return;
        int s = ei[e], d = ei[E + e];
        int pos = atomicAdd(&cursor[d], 1);
        col[pos] = s;
    } else {
        int row = (int)(((long)blockIdx.x * blockDim.x + threadIdx.x) >> 5);
        int lane = threadIdx.x & 31;
        if (row >= U_NODES) return;
        int z = blockIdx.y - 1;
        float* x = xbase + (size_t)z * SZ_X;
        const float* pref_m = pref + (size_t)z * U_NODES * D_LAT;
        float4 v = ((const float4*)(pref_m + (size_t)row * D_LAT))[lane];
        float ss = v.x * v.x + v.y * v.y + v.z * v.z + v.w * v.w;
        ss = warp_sum(ss);
        float s = 1.0f / fmaxf(sqrtf(ss), 1e-12f);
        v.x *= s; v.y *= s; v.z *= s; v.w *= s;
        ((float4*)(x + (size_t)row * D_LAT))[lane] = v;
    }
}

// ---------------- gathers ----------------
__global__ void words_gather(const int* __restrict__ rp, const int* __restrict__ words,
                             int W, const float* __restrict__ word_emb,
                             float* __restrict__ tfeat) {
    int it = (int)(((long)blockIdx.x * blockDim.x + threadIdx.x) >> 5);
    int lane = threadIdx.x & 31;
    if (it >= I_NODES) return;
    int beg = rp[it], end = rp[it + 1];
    float4 a = make_float4(0.f, 0.f, 0.f, 0.f);
    int j = beg;
    for (; j + 4 <= end; j += 4) {
        int w0 = words[W + j], w1 = words[W + j + 1], w2 = words[W + j + 2], w3 = words[W + j + 3];
        acc4(a, ((const float4*)(word_emb + (size_t)w0 * D_LAT))[lane]);
        acc4(a, ((const float4*)(word_emb + (size_t)w1 * D_LAT))[lane]);
        acc4(a, ((const float4*)(word_emb + (size_t)w2 * D_LAT))[lane]);
        acc4(a, ((const float4*)(word_emb + (size_t)w3 * D_LAT))[lane]);
    }
    for (; j < end; j++)
        acc4(a, ((const float4*)(word_emb + (size_t)words[W + j] * D_LAT))[lane]);
    float inv = 1.0f / (float)max(end - beg, 1);
    a.x *= inv; a.y *= inv; a.z *= inv; a.w *= inv;
    ((float4*)(tfeat + (size_t)it * D_LAT))[lane] = a;
}

__global__ void gather128_b(const int* __restrict__ rp, const int* __restrict__ col,
                            const float* __restrict__ xbase, float* __restrict__ aggbase) {
    int n = (int)(((long)blockIdx.x * blockDim.x + threadIdx.x) >> 5);
    int lane = threadIdx.x & 31;
    if (n >= N_NODES) return;
    int z = blockIdx.y;
    const float* x = xbase + (size_t)z * SZ_X;
    float* agg = aggbase + (size_t)z * SZ_X;
    int beg = rp[n], end = rp[n + 1];
    float4 a = make_float4(0.f, 0.f, 0.f, 0.f);
    int j = beg;
    for (; j + 4 <= end; j += 4) {
        int s0 = col[j], s1 = col[j + 1], s2 = col[j + 2], s3 = col[j + 3];
        acc4(a, ((const float4*)(x + (size_t)s0 * D_LAT))[lane]);
        acc4(a, ((const float4*)(x + (size_t)s1 * D_LAT))[lane]);
        acc4(a, ((const float4*)(x + (size_t)s2 * D_LAT))[lane]);
        acc4(a, ((const float4*)(x + (size_t)s3 * D_LAT))[lane]);
    }
    for (; j < end; j++)
        acc4(a, ((const float4*)(x + (size_t)col[j] * D_LAT))[lane]);
    ((float4*)(agg + (size_t)n * D_LAT))[lane] = a;
}

__global__ void gather64_b(const int* __restrict__ rp, const int* __restrict__ col,
                           const float* __restrict__ xbase, float* __restrict__ aggbase) {
    int n = (int)(((long)blockIdx.x * blockDim.x + threadIdx.x) >> 5);
    int lane = threadIdx.x & 31;
    if (n >= N_NODES) return;
    int z = blockIdx.y;
    const float* x = xbase + (size_t)z * SZ_X64;
    float* agg = aggbase + (size_t)z * SZ_X64;
    int beg = rp[n], end = rp[n + 1];
    float2 a = make_float2(0.f, 0.f);
    int j = beg;
    for (; j + 4 <= end; j += 4) {
        int s0 = col[j], s1 = col[j + 1], s2 = col[j + 2], s3 = col[j + 3];
        acc2(a, ((const float2*)(x + (size_t)s0 * D_X))[lane]);
        acc2(a, ((const float2*)(x + (size_t)s1 * D_X))[lane]);
        acc2(a, ((const float2*)(x + (size_t)s2 * D_X))[lane]);
        acc2(a, ((const float2*)(x + (size_t)s3 * D_X))[lane]);
    }
    for (; j < end; j++)
        acc2(a, ((const float2*)(x + (size_t)col[j] * D_X))[lane]);
    ((float2*)(agg + (size_t)n * D_X))[lane] = a;
}

// ---------------- final scoring ----------------
__global__ void final_kernel(const float* __restrict__ rep,
                             const int* __restrict__ users, const int* __restrict__ pos,
                             const int* __restrict__ neg, float* __restrict__ out, int Bn) {
    int gw = (int)(((long)blockIdx.x * blockDim.x + threadIdx.x) >> 5);
    int lane = threadIdx.x & 31;
    if (gw >= Bn) return;
    int u = users[gw], p = pos[gw], n = neg[gw];
    const size_t stride = (size_t)N_NODES * D_X;
    const float* r0 = rep;
    const float* r1 = rep + stride;
    const float* r2 = rep + 2 * stride;

    auto ld = [&](const float* base, int node) {
        return ((const float2*)(base + (size_t)node * D_X))[lane];
    };
    float2 t_u = ld(r2, u), t_p = ld(r2, p), t_n = ld(r2, n);
    float2 a_u = ld(r0, u), b_u = ld(r1, u);
    float2 a_p = ld(r0, p), b_p = ld(r1, p);
    float2 a_n = ld(r0, n), b_n = ld(r1, n);

    const float third = 1.0f / 3.0f;
    float2 pu = make_float2((a_u.x + b_u.x + t_u.x) * third, (a_u.y + b_u.y + t_u.y) * third);
    float2 pp = make_float2((a_p.x + b_p.x + t_p.x) * third, (a_p.y + b_p.y + t_p.y) * third);
    float2 pn = make_float2((a_n.x + b_n.x + t_n.x) * third, (a_n.y + b_n.y + t_n.y) * third);

    float prep  = t_u.x * t_p.x + t_u.y * t_p.y;
    float pren  = t_u.x * t_n.x + t_u.y * t_n.y;
    float postp = pu.x * pp.x + pu.y * pp.y;
    float postn = pu.x * pn.x + pu.y * pn.y;

    prep = warp_sum(prep);
    pren = warp_sum(pren);
    postp = warp_sum(postp);
    postn = warp_sum(postn);

    if (lane == 0) {
        float sp = 1.0f / (1.0f + expf(-prep));
        float sn = 1.0f / (1.0f + expf(-pren));
        out[gw]          = postp * sp;
        out[Bn + gw]     = postn * sn;
        out[2 * Bn + gw] = prep;
        out[3 * Bn + gw] = pren;
    }
}

// ---------------- host orchestration ----------------
static inline int nblk(long n, int t) { return (int)((n + t - 1) / t); }

extern "C" void kernel_launch(void* const* d_in, const int* in_sizes, int n_in,
                              void* d_out, int out_size) {
    const float* v_feat   = (const float*)d_in[0];
    const float* a_feat   = (const float*)d_in[1];
    const float* word_emb = (const float*)d_in[2];
    const float* id_emb   = (const float*)d_in[3];
    const float* pref     = (const float*)d_in[4];
    const float* mlp_w    = (const float*)d_in[5];
    const float* mlp_b    = (const float*)d_in[6];
    const float* conv1_w  = (const float*)d_in[7];
    const float* lin1_w   = (const float*)d_in[8];
    const float* lin1_b   = (const float*)d_in[9];
    const float* g1_w     = (const float*)d_in[10];
    const float* g1_b     = (const float*)d_in[11];
    const float* conv2_w  = (const float*)d_in[12];
    const float* lin2_w   = (const float*)d_in[13];
    const float* lin2_b   = (const float*)d_in[14];
    const float* g2_w     = (const float*)d_in[15];
    const float* g2_b     = (const float*)d_in[16];
    const int*   edges    = (const int*)d_in[17];
    const int*   words    = (const int*)d_in[18];
    const int*   users    = (const int*)d_in[19];
    const int*   posn     = (const int*)d_in[20];
    const int*   negn     = (const int*)d_in[21];

    const int E  = in_sizes[17] / 2;   // 500000
    const int W  = in_sizes[18] / 2;   // 600000
    const int Bn = in_sizes[19];       // 2048

    float* sc = nullptr;
    cudaGetSymbolAddress((void**)&sc, g_scratch);

    float* tfeat = sc + OFF_TFEAT;
    float* x     = sc + R_X;                       // stride SZ_X
    float* rep   = sc + R_X;                       // stride SZ_X64 (x dead at dual2)
    float* agg   = sc + R_AGG;                     // stride SZ_X
    float* h     = sc + R_H;                       // stride SZ_X; reused as h64
    float* x64   = sc + R_AGG;                     // stride SZ_X64 (agg dead after conv1)
    float* agg64 = sc + R_AGG + 3 * SZ_X64;        // stride SZ_X64

    int* ib     = (int*)(sc + OFF_CSR);
    int* cursor = ib + ICUR;
    int* rp     = ib + IRP;
    int* bsum   = ib + IBSUM;
    int* col    = ib + ICOL;
    int* wrp    = ib + IWRP;
    uint32_t* wf = (uint32_t*)(sc + OFF_WF);

    const int NB = nblk(N_NODES, 256);

    // dynamic smem opt-in (host attr; once)
    static bool attr_done = false;
    if (!attr_done) {
        cudaFuncSetAttribute((const void*)gemm_tc_f<128, 128, true, false, true>,
                             cudaFuncAttributeMaxDynamicSharedMemorySize, 65536);
        cudaFuncSetAttribute((const void*)gemm_tc_f<128, 128, false, true, false>,
                             cudaFuncAttributeMaxDynamicSharedMemorySize, 65536);
        cudaFuncSetAttribute((const void*)dual_gemm_tc_f<128>,
                             cudaFuncAttributeMaxDynamicSharedMemorySize, 65536);
        attr_done = true;
    }

    // 0: weight fragments (tf32, fragment order)
    prep_weights<<<nblk(WF_TOTAL, 256), 256>>>(mlp_w, lin1_w, g1_w, lin2_w, g2_w,
                                               conv1_w, conv2_w, wf);
    // 1: zero cursor + words row_ptr (merged)
    init_misc<<<nblk(W, 256), 256>>>(cursor, words, W, wrp);
    // 2: t_feat gather-mean
    words_gather<<<nblk((long)I_NODES * 32, 256), 256>>>(wrp, words, W, word_emb, tfeat);
    // 3: mlp GEMM + fused item-row normalize  <-- ncu capture target
    {
        dim3 grid(nblk(I_NODES, 128), 1, 3);
        gemm_tc_f<128, 128, true, false, true><<<grid, 256, 65536>>>(
            v_feat, a_feat, tfeat,
            wf + WF_MLP, 128 * 128, mlp_b, 128,
            x + (size_t)U_NODES * D_LAT, SZ_X, I_NODES, 128);
    }
    // 4-6: CSR histogram + scan
    deg_hist<<<nblk(E, 256), 256>>>(edges, E, cursor);
    deg_partials<<<NB, 256>>>(cursor, bsum, N_NODES);
    deg_scan<<<NB, 256>>>(cursor, bsum, rp, cursor, N_NODES);
    // 7: csr_fill + user-row normalize (merged)
    {
        dim3 grid(nblk((long)U_NODES * 32, 256), 4);
        csr_fill_norm<<<grid, 256>>>(edges, E, cursor, col, pref, x);
    }
    // 8: layer-1 gather
    {
        dim3 grid(nblk((long)N_NODES * 32, 256), 3);
        gather128_b<<<grid, 256>>>(rp, col, x, agg);
    }
    // 9: conv1 (full-K staging)
    {
        dim3 grid(nblk(N_NODES, 128), 1, 3);
        gemm_tc_f<128, 128, false, true, false><<<grid, 256, 65536>>>(
            agg, agg + SZ_X, agg + 2 * SZ_X,
            wf + WF_C1, 128 * 128, nullptr, 0,
            h, SZ_X, N_NODES, 128);
    }
    // 10: dual1 -> x64 (full-K sequential staging)
    {
        dim3 grid(nblk(N_NODES, 128), 1, 3);
        dual_gemm_tc_f<128><<<grid, 256, 65536>>>(
            x, SZ_X, wf + WF_LIN1, 128 * 64, lin1_b, 64,
            h, SZ_X, wf + WF_G1, 128 * 64, g1_b, 64,
            id_emb, x64, SZ_X64, N_NODES);
    }
    // 11: layer-2 gather
    {
        dim3 grid(nblk((long)N_NODES * 32, 256), 3);
        gather64_b<<<grid, 256>>>(rp, col, x64, agg64);
    }
    // 12: conv2 -> h64 (full-K staging, 32KB dynamic)
    {
        dim3 grid(nblk(N_NODES, 128), 1, 3);
        gemm_tc_f<64, 64, false, true, false><<<grid, 256, 32768>>>(
            agg64, agg64 + SZ_X64, agg64 + 2 * SZ_X64,
            wf + WF_C2, 64 * 64, nullptr, 0,
            h, SZ_X64, N_NODES, 64);
    }
    // 13: dual2 -> rep (full-K sequential staging, 32KB dynamic)
    {
        dim3 grid(nblk(N_NODES, 128), 1, 3);
        dual_gemm_tc_f<64><<<grid, 256, 32768>>>(
            x64, SZ_X64, wf + WF_LIN2, 64 * 64, lin2_b, 64,
            h, SZ_X64, wf + WF_G2, 64 * 64, g2_b, 64,
            id_emb, rep, SZ_X64, N_NODES);
    }
    // 14: final scoring
    final_kernel<<<nblk((long)Bn * 32, 256), 256>>>(rep, users, posn, negn,
                                                    (float*)d_out, Bn);
}